// round 12
// baseline (speedup 1.0000x reference)
#include <cuda_runtime.h>
#include <cuda_bf16.h>

#define NTHREADS 256
#define MAX_BLOCKS 2048

__device__ float2 g_partials[MAX_BLOCKS];
__device__ unsigned int g_ticket = 0;   // self-resetting via atomicInc wrap

__device__ __forceinline__ float4 ldcg_f4(const float4* p) {
    float4 v;
    asm volatile("ld.global.cg.v4.f32 {%0, %1, %2, %3}, [%4];"
                 : "=f"(v.x), "=f"(v.y), "=f"(v.z), "=f"(v.w) : "l"(p));
    return v;
}

__device__ __forceinline__ void accum_elem(float x, float p, float n, float y,
                                           float& s_bce, float& s_cnt) {
    float m   = (fminf(p, n) > 0.5f) ? 1.0f : 0.0f;
    float t   = __expf(-fabsf(x));                       // FMUL + MUFU.EX2
    float sp  = 0.69314718056f * __log2f(1.0f + t);      // FADD + MUFU.LG2 + FMUL
    float bce = fmaxf(x, 0.0f) - x * y + sp;
    s_bce += bce * m;
    s_cnt += m;
}

__device__ __forceinline__ void accum_vec(float4 xv, float4 pv, float4 nv, float y,
                                          float& s_bce, float& s_cnt) {
    accum_elem(xv.x, pv.x, nv.x, y, s_bce, s_cnt);
    accum_elem(xv.y, pv.y, nv.y, y, s_bce, s_cnt);
    accum_elem(xv.z, pv.z, nv.z, y, s_bce, s_cnt);
    accum_elem(xv.w, pv.w, nv.w, y, s_bce, s_cnt);
}

__global__ __launch_bounds__(NTHREADS) void loss_kernel(
    const float4* __restrict__ x4,
    const float*  __restrict__ label,
    const float4* __restrict__ pm4,
    const float4* __restrict__ nm4,
    float* __restrict__ out,
    int hw4, int iters, int nblocks_total)
{
    const int   b    = blockIdx.y;
    const float y    = __ldg(&label[b]);
    const int   base = b * hw4;

    float s_bce = 0.0f;
    float s_cnt = 0.0f;

    const int stride = gridDim.x * blockDim.x;
    int i = blockIdx.x * blockDim.x + threadIdx.x;

    // Perfectly uniform counted mainloop: 1024 blocks x 256 thr over
    // hw4=65536 float4s/image -> exactly 8 iterations per thread,
    // no bounds check, no work imbalance. Default-policy __ldg loads
    // (proven best for wall-time L2 retention across graph replays).
    for (int it = 0; it < iters; ++it, i += stride) {
        float4 xv = __ldg(&x4 [base + i]);
        float4 pv = __ldg(&pm4[base + i]);
        float4 nv = __ldg(&nm4[base + i]);
        accum_vec(xv, pv, nv, y, s_bce, s_cnt);
    }
    // Generic tail (empty when evenly divisible)
    for (; i < hw4; i += stride) {
        float4 xv = __ldg(&x4 [base + i]);
        float4 pv = __ldg(&pm4[base + i]);
        float4 nv = __ldg(&nm4[base + i]);
        accum_vec(xv, pv, nv, y, s_bce, s_cnt);
    }

    // Warp reduction
    #pragma unroll
    for (int off = 16; off > 0; off >>= 1) {
        s_bce += __shfl_down_sync(0xFFFFFFFFu, s_bce, off);
        s_cnt += __shfl_down_sync(0xFFFFFFFFu, s_cnt, off);
    }

    // Block reduction
    __shared__ float sh_bce[8];
    __shared__ float sh_cnt[8];
    const int wid = threadIdx.x >> 5;
    const int lid = threadIdx.x & 31;
    if (lid == 0) { sh_bce[wid] = s_bce; sh_cnt[wid] = s_cnt; }
    __syncthreads();

    __shared__ bool is_last;
    const int blin = blockIdx.y * gridDim.x + blockIdx.x;
    if (threadIdx.x < 32) {
        float bsum = (lid < (NTHREADS >> 5)) ? sh_bce[lid] : 0.0f;
        float csum = (lid < (NTHREADS >> 5)) ? sh_cnt[lid] : 0.0f;
        #pragma unroll
        for (int off = 4; off > 0; off >>= 1) {
            bsum += __shfl_down_sync(0xFFFFFFFFu, bsum, off);
            csum += __shfl_down_sync(0xFFFFFFFFu, csum, off);
        }
        if (lid == 0) {
            g_partials[blin] = make_float2(bsum, csum);
            __threadfence();
            unsigned t = atomicInc(&g_ticket, (unsigned)nblocks_total - 1);
            is_last = (t == (unsigned)nblocks_total - 1);
        }
    }
    __syncthreads();

    if (is_last) {
        // nblocks_total is even: two float2 partials per v4 load.
        double db = 0.0, dc = 0.0;
        const int npairs = nblocks_total >> 1;
        for (int k = threadIdx.x; k < npairs; k += blockDim.x) {
            float4 p = ldcg_f4((const float4*)&g_partials[k * 2]);
            db += (double)p.x + (double)p.z;
            dc += (double)p.y + (double)p.w;
        }
        #pragma unroll
        for (int off = 16; off > 0; off >>= 1) {
            db += __shfl_down_sync(0xFFFFFFFFu, db, off);
            dc += __shfl_down_sync(0xFFFFFFFFu, dc, off);
        }
        __shared__ double dh_b[8];
        __shared__ double dh_c[8];
        if (lid == 0) { dh_b[wid] = db; dh_c[wid] = dc; }
        __syncthreads();
        if (threadIdx.x < 32) {
            double b2 = (lid < (NTHREADS >> 5)) ? dh_b[lid] : 0.0;
            double c2 = (lid < (NTHREADS >> 5)) ? dh_c[lid] : 0.0;
            #pragma unroll
            for (int off = 4; off > 0; off >>= 1) {
                b2 += __shfl_down_sync(0xFFFFFFFFu, b2, off);
                c2 += __shfl_down_sync(0xFFFFFFFFu, c2, off);
            }
            if (lid == 0) {
                if (c2 < 1.0) c2 = 1.0;
                out[0] = (float)(b2 / c2);
            }
        }
    }
}

extern "C" void kernel_launch(void* const* d_in, const int* in_sizes, int n_in,
                              void* d_out, int out_size) {
    const float* x  = (const float*)d_in[0];  // cancer_logits (B,1,H,W)
    const float* y  = (const float*)d_in[1];  // label (B,)
    const float* pm = (const float*)d_in[2];  // prostate_mask
    const float* nm = (const float*)d_in[3];  // needle_mask

    int n   = in_sizes[0];   // B*H*W
    int nb  = in_sizes[1];   // B
    int hw4 = (n / nb) / 4;  // float4s per image (65536 for 512x512)

    // bpb=32, B=32 -> 1024 blocks; 32 regs -> 8 blocks/SM -> capacity 1184:
    // single wave. 8192 threads/image -> exactly hw4/8192 = 8 uniform iters.
    int bpb = 32;
    while (bpb * nb > MAX_BLOCKS && bpb > 1) bpb >>= 1;
    int nblocks_total = bpb * nb;
    int tpi   = bpb * NTHREADS;
    int iters = hw4 / tpi;

    dim3 grid(bpb, nb, 1);
    loss_kernel<<<grid, NTHREADS>>>(
        (const float4*)x, y, (const float4*)pm, (const float4*)nm,
        (float*)d_out, hw4, iters, nblocks_total);
}

// round 13
// speedup vs baseline: 1.0133x; 1.0133x over previous
#include <cuda_runtime.h>
#include <cuda_bf16.h>

#define NTHREADS 256
#define MAX_BLOCKS 2048

__device__ float2 g_partials[MAX_BLOCKS];
__device__ unsigned int g_ticket = 0;   // self-resetting via atomicInc wrap

__device__ __forceinline__ float2 ldcg_f2(const float2* p) {
    float2 v;
    asm volatile("ld.global.cg.v2.f32 {%0, %1}, [%2];"
                 : "=f"(v.x), "=f"(v.y) : "l"(p));
    return v;
}

struct f8 { float v[8]; };

// 256-bit read-only load, L2 evict_last — the best-measured variant (16.864us).
__device__ __forceinline__ f8 ldg_el8(const float* p) {
    f8 r;
    asm("ld.global.nc.L2::evict_last.v8.b32 {%0,%1,%2,%3,%4,%5,%6,%7}, [%8];"
        : "=f"(r.v[0]), "=f"(r.v[1]), "=f"(r.v[2]), "=f"(r.v[3]),
          "=f"(r.v[4]), "=f"(r.v[5]), "=f"(r.v[6]), "=f"(r.v[7])
        : "l"(p));
    return r;
}

__device__ __forceinline__ void accum_elem(float x, float p, float n, float y,
                                           float& s_bce, float& s_cnt) {
    float m   = (fminf(p, n) > 0.5f) ? 1.0f : 0.0f;
    float t   = __expf(-fabsf(x));                       // FMUL + MUFU.EX2
    float sp  = 0.69314718056f * __log2f(1.0f + t);      // FADD + MUFU.LG2 + FMUL
    float bce = fmaxf(x, 0.0f) - x * y + sp;
    s_bce += bce * m;
    s_cnt += m;
}

__global__ __launch_bounds__(NTHREADS) void loss_kernel(
    const float* __restrict__ x,
    const float* __restrict__ label,
    const float* __restrict__ pm,
    const float* __restrict__ nm,
    float* __restrict__ out,
    int hw8, int nblocks_total)
{
    const int   b    = blockIdx.y;
    const float y    = __ldg(&label[b]);
    const long long base = (long long)b * hw8 * 8;   // float offset of this image

    float s_bce = 0.0f;
    float s_cnt = 0.0f;

    const int stride = gridDim.x * blockDim.x;
    for (int i = blockIdx.x * blockDim.x + threadIdx.x; i < hw8; i += stride) {
        const long long off = base + (long long)i * 8;
        f8 xv = ldg_el8(x  + off);
        f8 pv = ldg_el8(pm + off);
        f8 nv = ldg_el8(nm + off);
        #pragma unroll
        for (int k = 0; k < 8; ++k)
            accum_elem(xv.v[k], pv.v[k], nv.v[k], y, s_bce, s_cnt);
    }

    // Warp reduction
    #pragma unroll
    for (int off = 16; off > 0; off >>= 1) {
        s_bce += __shfl_down_sync(0xFFFFFFFFu, s_bce, off);
        s_cnt += __shfl_down_sync(0xFFFFFFFFu, s_cnt, off);
    }

    // Block reduction
    __shared__ float sh_bce[8];
    __shared__ float sh_cnt[8];
    const int wid = threadIdx.x >> 5;
    const int lid = threadIdx.x & 31;
    if (lid == 0) { sh_bce[wid] = s_bce; sh_cnt[wid] = s_cnt; }
    __syncthreads();

    __shared__ bool is_last;
    const int blin = blockIdx.y * gridDim.x + blockIdx.x;
    if (threadIdx.x < 32) {
        float bsum = (lid < (NTHREADS >> 5)) ? sh_bce[lid] : 0.0f;
        float csum = (lid < (NTHREADS >> 5)) ? sh_cnt[lid] : 0.0f;
        #pragma unroll
        for (int off = 4; off > 0; off >>= 1) {
            bsum += __shfl_down_sync(0xFFFFFFFFu, bsum, off);
            csum += __shfl_down_sync(0xFFFFFFFFu, csum, off);
        }
        if (lid == 0) {
            g_partials[blin] = make_float2(bsum, csum);
            __threadfence();
            unsigned t = atomicInc(&g_ticket, (unsigned)nblocks_total - 1);
            is_last = (t == (unsigned)nblocks_total - 1);
        }
    }
    __syncthreads();

    if (is_last) {
        double db = 0.0, dc = 0.0;
        for (int k = threadIdx.x; k < nblocks_total; k += blockDim.x) {
            float2 p = ldcg_f2(&g_partials[k]);
            db += (double)p.x;
            dc += (double)p.y;
        }
        #pragma unroll
        for (int off = 16; off > 0; off >>= 1) {
            db += __shfl_down_sync(0xFFFFFFFFu, db, off);
            dc += __shfl_down_sync(0xFFFFFFFFu, dc, off);
        }
        __shared__ double dh_b[8];
        __shared__ double dh_c[8];
        if (lid == 0) { dh_b[wid] = db; dh_c[wid] = dc; }
        __syncthreads();
        if (threadIdx.x < 32) {
            double b2 = (lid < (NTHREADS >> 5)) ? dh_b[lid] : 0.0;
            double c2 = (lid < (NTHREADS >> 5)) ? dh_c[lid] : 0.0;
            #pragma unroll
            for (int off = 4; off > 0; off >>= 1) {
                b2 += __shfl_down_sync(0xFFFFFFFFu, b2, off);
                c2 += __shfl_down_sync(0xFFFFFFFFu, c2, off);
            }
            if (lid == 0) {
                if (c2 < 1.0) c2 = 1.0;
                out[0] = (float)(b2 / c2);
            }
        }
    }
}

extern "C" void kernel_launch(void* const* d_in, const int* in_sizes, int n_in,
                              void* d_out, int out_size) {
    const float* x  = (const float*)d_in[0];  // cancer_logits (B,1,H,W)
    const float* y  = (const float*)d_in[1];  // label (B,)
    const float* pm = (const float*)d_in[2];  // prostate_mask
    const float* nm = (const float*)d_in[3];  // needle_mask

    int n   = in_sizes[0];   // B*H*W
    int nb  = in_sizes[1];   // B
    int hw8 = (n / nb) / 8;  // float8s per image

    // Best-measured config (R7, 16.864us): 40 regs -> 6 blocks/SM; single
    // wave requires bpb * nb <= 6 * 148 = 888. For nb=32: bpb=27 -> 864.
    int bpb = (6 * 148) / nb;
    if (bpb < 1) bpb = 1;
    while (bpb * nb > MAX_BLOCKS && bpb > 1) bpb--;
    int nblocks_total = bpb * nb;

    dim3 grid(bpb, nb, 1);
    loss_kernel<<<grid, NTHREADS>>>(
        x, y, pm, nm, (float*)d_out, hw8, nblocks_total);
}

// round 14
// speedup vs baseline: 1.0229x; 1.0096x over previous
#include <cuda_runtime.h>
#include <cuda_bf16.h>

#define NTHREADS 256

__device__ double g_dacc[2] = {0.0, 0.0};   // [0]=sum(bce*m), [1]=sum(m); last block resets
__device__ unsigned int g_ticket = 0;       // self-resetting via atomicInc wrap

struct f8 { float v[8]; };

// 256-bit read-only load, L2 evict_last — best-measured mainloop variant.
__device__ __forceinline__ f8 ldg_el8(const float* p) {
    f8 r;
    asm("ld.global.nc.L2::evict_last.v8.b32 {%0,%1,%2,%3,%4,%5,%6,%7}, [%8];"
        : "=f"(r.v[0]), "=f"(r.v[1]), "=f"(r.v[2]), "=f"(r.v[3]),
          "=f"(r.v[4]), "=f"(r.v[5]), "=f"(r.v[6]), "=f"(r.v[7])
        : "l"(p));
    return r;
}

__device__ __forceinline__ void red_add_f64(double* p, double v) {
    asm volatile("red.global.add.f64 [%0], %1;" :: "l"(p), "d"(v) : "memory");
}

__device__ __forceinline__ double ldcg_f64(const double* p) {
    double v;
    asm volatile("ld.global.cg.f64 %0, [%1];" : "=d"(v) : "l"(p));
    return v;
}

__device__ __forceinline__ void accum_elem(float x, float p, float n, float y,
                                           float& s_bce, float& s_cnt) {
    float m   = (fminf(p, n) > 0.5f) ? 1.0f : 0.0f;
    float t   = __expf(-fabsf(x));                       // FMUL + MUFU.EX2
    float sp  = 0.69314718056f * __log2f(1.0f + t);      // FADD + MUFU.LG2 + FMUL
    float bce = fmaxf(x, 0.0f) - x * y + sp;
    s_bce += bce * m;
    s_cnt += m;
}

__global__ __launch_bounds__(NTHREADS) void loss_kernel(
    const float* __restrict__ x,
    const float* __restrict__ label,
    const float* __restrict__ pm,
    const float* __restrict__ nm,
    float* __restrict__ out,
    int hw8, int nblocks_total)
{
    const int   b    = blockIdx.y;
    const float y    = __ldg(&label[b]);
    const long long base = (long long)b * hw8 * 8;   // float offset of this image

    float s_bce = 0.0f;
    float s_cnt = 0.0f;

    const int stride = gridDim.x * blockDim.x;
    for (int i = blockIdx.x * blockDim.x + threadIdx.x; i < hw8; i += stride) {
        const long long off = base + (long long)i * 8;
        f8 xv = ldg_el8(x  + off);
        f8 pv = ldg_el8(pm + off);
        f8 nv = ldg_el8(nm + off);
        #pragma unroll
        for (int k = 0; k < 8; ++k)
            accum_elem(xv.v[k], pv.v[k], nv.v[k], y, s_bce, s_cnt);
    }

    // Warp reduction
    #pragma unroll
    for (int off = 16; off > 0; off >>= 1) {
        s_bce += __shfl_down_sync(0xFFFFFFFFu, s_bce, off);
        s_cnt += __shfl_down_sync(0xFFFFFFFFu, s_cnt, off);
    }

    // Block reduction
    __shared__ float sh_bce[8];
    __shared__ float sh_cnt[8];
    const int wid = threadIdx.x >> 5;
    const int lid = threadIdx.x & 31;
    if (lid == 0) { sh_bce[wid] = s_bce; sh_cnt[wid] = s_cnt; }
    __syncthreads();

    if (threadIdx.x < 32) {
        float bsum = (lid < (NTHREADS >> 5)) ? sh_bce[lid] : 0.0f;
        float csum = (lid < (NTHREADS >> 5)) ? sh_cnt[lid] : 0.0f;
        #pragma unroll
        for (int off = 4; off > 0; off >>= 1) {
            bsum += __shfl_down_sync(0xFFFFFFFFu, bsum, off);
            csum += __shfl_down_sync(0xFFFFFFFFu, csum, off);
        }
        if (lid == 0) {
            // Fire-and-forget double reds: staggered block finishes hide the
            // per-address LTS serialization under the mainloop drain.
            red_add_f64(&g_dacc[0], (double)bsum);
            red_add_f64(&g_dacc[1], (double)csum);
            __threadfence();
            // Wrapping ticket: red -> fence -> inc means the final incrementer
            // observes every block's contribution.
            unsigned t = atomicInc(&g_ticket, (unsigned)nblocks_total - 1);
            if (t == (unsigned)nblocks_total - 1) {
                double b2 = ldcg_f64(&g_dacc[0]);
                double c2 = ldcg_f64(&g_dacc[1]);
                // Reset for the next graph replay (self-cleaning).
                g_dacc[0] = 0.0;
                g_dacc[1] = 0.0;
                if (c2 < 1.0) c2 = 1.0;
                out[0] = (float)(b2 / c2);
            }
        }
    }
}

extern "C" void kernel_launch(void* const* d_in, const int* in_sizes, int n_in,
                              void* d_out, int out_size) {
    const float* x  = (const float*)d_in[0];  // cancer_logits (B,1,H,W)
    const float* y  = (const float*)d_in[1];  // label (B,)
    const float* pm = (const float*)d_in[2];  // prostate_mask
    const float* nm = (const float*)d_in[3];  // needle_mask

    int n   = in_sizes[0];   // B*H*W
    int nb  = in_sizes[1];   // B
    int hw8 = (n / nb) / 8;  // float8s per image

    // Best-measured grid (R7): 40 regs -> 6 blocks/SM; single wave requires
    // bpb * nb <= 6 * 148 = 888. For nb=32: bpb=27 -> 864 blocks.
    int bpb = (6 * 148) / nb;
    if (bpb < 1) bpb = 1;
    int nblocks_total = bpb * nb;

    dim3 grid(bpb, nb, 1);
    loss_kernel<<<grid, NTHREADS>>>(
        x, y, pm, nm, (float*)d_out, hw8, nblocks_total);
}

// round 15
// speedup vs baseline: 1.0409x; 1.0175x over previous
#include <cuda_runtime.h>
#include <cuda_bf16.h>

#define NTHREADS 256
#define MAX_BLOCKS 2048

__device__ double g_dacc[2] = {0.0, 0.0};   // [0]=sum(bce*m), [1]=sum(m); last block resets
__device__ unsigned int g_ticket = 0;       // self-resetting via atomicInc wrap

// Fire-and-forget reduction with release semantics: orders this block's
// contribution before the subsequent atomicInc without a separate MEMBAR.
__device__ __forceinline__ void red_release_f64(double* p, double v) {
    asm volatile("red.release.gpu.global.add.f64 [%0], %1;" :: "l"(p), "d"(v) : "memory");
}

__device__ __forceinline__ double ldcg_f64(const double* p) {
    double v;
    asm volatile("ld.global.cg.f64 %0, [%1];" : "=d"(v) : "l"(p));
    return v;
}

__device__ __forceinline__ void accum_elem(float x, float p, float n, float y,
                                           float& s_bce, float& s_cnt) {
    float m   = (fminf(p, n) > 0.5f) ? 1.0f : 0.0f;
    float t   = __expf(-fabsf(x));                       // FMUL + MUFU.EX2
    float sp  = 0.69314718056f * __log2f(1.0f + t);      // FADD + MUFU.LG2 + FMUL
    float bce = fmaxf(x, 0.0f) - x * y + sp;
    s_bce += bce * m;
    s_cnt += m;
}

__device__ __forceinline__ void accum_vec(float4 xv, float4 pv, float4 nv, float y,
                                          float& s_bce, float& s_cnt) {
    accum_elem(xv.x, pv.x, nv.x, y, s_bce, s_cnt);
    accum_elem(xv.y, pv.y, nv.y, y, s_bce, s_cnt);
    accum_elem(xv.z, pv.z, nv.z, y, s_bce, s_cnt);
    accum_elem(xv.w, pv.w, nv.w, y, s_bce, s_cnt);
}

__global__ __launch_bounds__(NTHREADS) void loss_kernel(
    const float4* __restrict__ x4,
    const float*  __restrict__ label,
    const float4* __restrict__ pm4,
    const float4* __restrict__ nm4,
    float* __restrict__ out,
    int hw4, int nblocks_total)
{
    const int   b    = blockIdx.y;
    const float y    = __ldg(&label[b]);
    const int   base = b * hw4;

    float s_bce = 0.0f;
    float s_cnt = 0.0f;

    // v4 loads keep regs at 32 -> 8 blocks/SM -> 1184-block grid fills the
    // chip exactly (148 SMs x 8), max warps in flight for latency hiding.
    const int stride = gridDim.x * blockDim.x;
    for (int i = blockIdx.x * blockDim.x + threadIdx.x; i < hw4; i += stride) {
        float4 xv = __ldg(&x4 [base + i]);
        float4 pv = __ldg(&pm4[base + i]);
        float4 nv = __ldg(&nm4[base + i]);
        accum_vec(xv, pv, nv, y, s_bce, s_cnt);
    }

    // Warp reduction
    #pragma unroll
    for (int off = 16; off > 0; off >>= 1) {
        s_bce += __shfl_down_sync(0xFFFFFFFFu, s_bce, off);
        s_cnt += __shfl_down_sync(0xFFFFFFFFu, s_cnt, off);
    }

    // Block reduction
    __shared__ float sh_bce[8];
    __shared__ float sh_cnt[8];
    const int wid = threadIdx.x >> 5;
    const int lid = threadIdx.x & 31;
    if (lid == 0) { sh_bce[wid] = s_bce; sh_cnt[wid] = s_cnt; }
    __syncthreads();

    if (threadIdx.x < 32) {
        float bsum = (lid < (NTHREADS >> 5)) ? sh_bce[lid] : 0.0f;
        float csum = (lid < (NTHREADS >> 5)) ? sh_cnt[lid] : 0.0f;
        #pragma unroll
        for (int off = 4; off > 0; off >>= 1) {
            bsum += __shfl_down_sync(0xFFFFFFFFu, bsum, off);
            csum += __shfl_down_sync(0xFFFFFFFFu, csum, off);
        }
        if (lid == 0) {
            // Release-ordered reds, then the wrapping ticket. The final
            // incrementer's acquire pairs with every block's release.
            red_release_f64(&g_dacc[0], (double)bsum);
            red_release_f64(&g_dacc[1], (double)csum);
            unsigned t;
            asm volatile("atom.acquire.gpu.global.inc.u32 %0, [%1], %2;"
                         : "=r"(t) : "l"(&g_ticket), "r"((unsigned)nblocks_total - 1)
                         : "memory");
            if (t == (unsigned)nblocks_total - 1) {
                double b2 = ldcg_f64(&g_dacc[0]);
                double c2 = ldcg_f64(&g_dacc[1]);
                // Reset for the next graph replay (self-cleaning).
                g_dacc[0] = 0.0;
                g_dacc[1] = 0.0;
                if (c2 < 1.0) c2 = 1.0;
                out[0] = (float)(b2 / c2);
            }
        }
    }
}

extern "C" void kernel_launch(void* const* d_in, const int* in_sizes, int n_in,
                              void* d_out, int out_size) {
    const float* x  = (const float*)d_in[0];  // cancer_logits (B,1,H,W)
    const float* y  = (const float*)d_in[1];  // label (B,)
    const float* pm = (const float*)d_in[2];  // prostate_mask
    const float* nm = (const float*)d_in[3];  // needle_mask

    int n   = in_sizes[0];   // B*H*W
    int nb  = in_sizes[1];   // B
    int hw4 = (n / nb) / 4;  // float4s per image

    // 32 regs -> 8 blocks/SM; fill the chip exactly: bpb*nb = 1184.
    int bpb = (8 * 148 + nb - 1) / nb;            // 37 for B=32
    if (bpb * nb > MAX_BLOCKS) bpb = MAX_BLOCKS / nb;
    int nblocks_total = bpb * nb;

    dim3 grid(bpb, nb, 1);
    loss_kernel<<<grid, NTHREADS>>>(
        (const float4*)x, y, (const float4*)pm, (const float4*)nm,
        (float*)d_out, hw4, nblocks_total);
}

// round 16
// speedup vs baseline: 1.1555x; 1.1102x over previous
#include <cuda_runtime.h>
#include <cuda_bf16.h>

#define NTHREADS 512
#define MAX_BLOCKS 2048

__device__ double g_dacc[2] = {0.0, 0.0};   // [0]=sum(bce*m), [1]=sum(m); last block resets
__device__ unsigned int g_ticket = 0;       // self-resetting via atomicInc wrap

// Fire-and-forget reduction with release semantics.
__device__ __forceinline__ void red_release_f64(double* p, double v) {
    asm volatile("red.release.gpu.global.add.f64 [%0], %1;" :: "l"(p), "d"(v) : "memory");
}

__device__ __forceinline__ double ldcg_f64(const double* p) {
    double v;
    asm volatile("ld.global.cg.f64 %0, [%1];" : "=d"(v) : "l"(p));
    return v;
}

__device__ __forceinline__ void accum_elem(float x, float p, float n, float y,
                                           float& s_bce, float& s_cnt) {
    float m   = (fminf(p, n) > 0.5f) ? 1.0f : 0.0f;
    float t   = __expf(-fabsf(x));                       // FMUL + MUFU.EX2
    float sp  = 0.69314718056f * __log2f(1.0f + t);      // FADD + MUFU.LG2 + FMUL
    float bce = fmaxf(x, 0.0f) - x * y + sp;
    s_bce += bce * m;
    s_cnt += m;
}

__device__ __forceinline__ void accum_vec(float4 xv, float4 pv, float4 nv, float y,
                                          float& s_bce, float& s_cnt) {
    accum_elem(xv.x, pv.x, nv.x, y, s_bce, s_cnt);
    accum_elem(xv.y, pv.y, nv.y, y, s_bce, s_cnt);
    accum_elem(xv.z, pv.z, nv.z, y, s_bce, s_cnt);
    accum_elem(xv.w, pv.w, nv.w, y, s_bce, s_cnt);
}

__global__ __launch_bounds__(NTHREADS) void loss_kernel(
    const float4* __restrict__ x4,
    const float*  __restrict__ label,
    const float4* __restrict__ pm4,
    const float4* __restrict__ nm4,
    float* __restrict__ out,
    int hw4, int nblocks_total)
{
    const int   b    = blockIdx.y;
    const float y    = __ldg(&label[b]);
    const int   base = b * hw4;

    float s_bce = 0.0f;
    float s_cnt = 0.0f;

    // 512 thr/block x 4 blocks/SM = 2048 threads/SM (same 64 warps as R15)
    // but HALF the blocks -> half the epilogue cost and contended-red traffic.
    const int stride = gridDim.x * blockDim.x;
    for (int i = blockIdx.x * blockDim.x + threadIdx.x; i < hw4; i += stride) {
        float4 xv = __ldg(&x4 [base + i]);
        float4 pv = __ldg(&pm4[base + i]);
        float4 nv = __ldg(&nm4[base + i]);
        accum_vec(xv, pv, nv, y, s_bce, s_cnt);
    }

    // Warp reduction
    #pragma unroll
    for (int off = 16; off > 0; off >>= 1) {
        s_bce += __shfl_down_sync(0xFFFFFFFFu, s_bce, off);
        s_cnt += __shfl_down_sync(0xFFFFFFFFu, s_cnt, off);
    }

    // Block reduction (16 warps)
    __shared__ float sh_bce[16];
    __shared__ float sh_cnt[16];
    const int wid = threadIdx.x >> 5;
    const int lid = threadIdx.x & 31;
    if (lid == 0) { sh_bce[wid] = s_bce; sh_cnt[wid] = s_cnt; }
    __syncthreads();

    if (threadIdx.x < 32) {
        float bsum = (lid < (NTHREADS >> 5)) ? sh_bce[lid] : 0.0f;
        float csum = (lid < (NTHREADS >> 5)) ? sh_cnt[lid] : 0.0f;
        #pragma unroll
        for (int off = 8; off > 0; off >>= 1) {
            bsum += __shfl_down_sync(0xFFFFFFFFu, bsum, off);
            csum += __shfl_down_sync(0xFFFFFFFFu, csum, off);
        }
        if (lid == 0) {
            red_release_f64(&g_dacc[0], (double)bsum);
            red_release_f64(&g_dacc[1], (double)csum);
            unsigned t;
            asm volatile("atom.acquire.gpu.global.inc.u32 %0, [%1], %2;"
                         : "=r"(t) : "l"(&g_ticket), "r"((unsigned)nblocks_total - 1)
                         : "memory");
            if (t == (unsigned)nblocks_total - 1) {
                double b2 = ldcg_f64(&g_dacc[0]);
                double c2 = ldcg_f64(&g_dacc[1]);
                // Reset for the next graph replay (self-cleaning).
                g_dacc[0] = 0.0;
                g_dacc[1] = 0.0;
                if (c2 < 1.0) c2 = 1.0;
                out[0] = (float)(b2 / c2);
            }
        }
    }
}

extern "C" void kernel_launch(void* const* d_in, const int* in_sizes, int n_in,
                              void* d_out, int out_size) {
    const float* x  = (const float*)d_in[0];  // cancer_logits (B,1,H,W)
    const float* y  = (const float*)d_in[1];  // label (B,)
    const float* pm = (const float*)d_in[2];  // prostate_mask
    const float* nm = (const float*)d_in[3];  // needle_mask

    int n   = in_sizes[0];   // B*H*W
    int nb  = in_sizes[1];   // B
    int hw4 = (n / nb) / 4;  // float4s per image

    // 4 blocks/SM at 512 threads -> capacity 592 blocks; single wave needs
    // bpb * nb <= 592. For nb=32: bpb=18 -> 576 blocks.
    int bpb = (4 * 148) / nb;
    if (bpb < 1) bpb = 1;
    while (bpb * nb > MAX_BLOCKS && bpb > 1) bpb--;
    int nblocks_total = bpb * nb;

    dim3 grid(bpb, nb, 1);
    loss_kernel<<<grid, NTHREADS>>>(
        (const float4*)x, y, (const float4*)pm, (const float4*)nm,
        (float*)d_out, hw4, nblocks_total);
}